// round 15
// baseline (speedup 1.0000x reference)
#include <cuda_runtime.h>

#define NUM_LEVELS 16
#define TABLE_SZ   16384
#define CHUNKS     9
#define THREADS    1024
#define MAX_B      262144

// floor(16 * 1.38^l) computed in double precision, exactly representable in f32
__constant__ float c_res[NUM_LEVELS] = {
    16.f, 22.f, 30.f, 42.f, 58.f, 80.f, 110.f, 152.f,
    210.f, 290.f, 400.f, 553.f, 763.f, 1053.f, 1453.f, 2005.f
};

// Scratch (allocation-free rule: __device__ globals)
__device__ float4 g_xs[MAX_B];                       // packed positions (4 MB)
__device__ float2 g_scr[NUM_LEVELS * MAX_B];         // [level][b] features (33.5 MB)

extern __shared__ float2 s_tab[];  // main: 16384 float2 = 128 KB

// Host-side stream/event fork (created once at load; host resources only,
// no device memory — legal under the allocation guards and capture rules).
static cudaStream_t s2;
static cudaEvent_t evA, evB, evC, evD;
static struct StreamInit {
    StreamInit() {
        cudaStreamCreateWithFlags(&s2, cudaStreamNonBlocking);
        cudaEventCreateWithFlags(&evA, cudaEventDisableTiming);
        cudaEventCreateWithFlags(&evB, cudaEventDisableTiming);
        cudaEventCreateWithFlags(&evC, cudaEventDisableTiming);
        cudaEventCreateWithFlags(&evD, cudaEventDisableTiming);
    }
} s_stream_init;

// ---------------------------------------------------------------- pack x
// Range [bstart, bend); bstart divisible by 4 so float4 indexing stays exact.
__global__ __launch_bounds__(256)
void pack_x_kernel(const float4* __restrict__ x4, int bstart, int bend)
{
    __shared__ float sx[256 * 3];
    const int b0 = bstart + blockIdx.x * 256;
    const int t  = threadIdx.x;
    if (t < 192) {
        float4 v = x4[(size_t)(b0 * 3) / 4 + t];
        sx[4 * t + 0] = v.x; sx[4 * t + 1] = v.y;
        sx[4 * t + 2] = v.z; sx[4 * t + 3] = v.w;
    }
    __syncthreads();
    const int b = b0 + t;
    if (b < bend)
        g_xs[b] = make_float4(sx[3 * t], sx[3 * t + 1], sx[3 * t + 2], 0.f);
}

// ---------------------------------------------------------------- main
__device__ __forceinline__ void hash_point(const float px, const float py,
                                           const float pz, const float res,
                                           float& ox, float& oy)
{
    // Interpolation weights use the UNSCALED position (faithful to source)
    const float wx = px - floorf(px);
    const float wy = py - floorf(py);
    const float wz = pz - floorf(pz);

    const float sx = res * px;
    const float sy = res * py;
    const float sz = res * pz;

    const int lx = __float2int_rd(sx);
    const int ly = __float2int_rd(sy);
    const int lz = __float2int_rd(sz);
    const int hx = __float2int_ru(sx);
    const int hy = __float2int_ru(sy);
    const int hz = __float2int_ru(sz);

    // int32 wraparound multiply == uint32 multiply (same bits);
    // python remainder by 16384 == & 16383 on two's complement
    const unsigned ay0 = 2654435761u * (unsigned)ly;
    const unsigned ay1 = 2654435761u * (unsigned)hy;
    const unsigned az0 = 805459861u  * (unsigned)lz;
    const unsigned az1 = 805459861u  * (unsigned)hz;

    const unsigned b00 = ay0 ^ az0;
    const unsigned b10 = ay1 ^ az0;
    const unsigned b01 = ay0 ^ az1;
    const unsigned b11 = ay1 ^ az1;
    const unsigned ux = (unsigned)lx;
    const unsigned vx = (unsigned)hx;

    // Corner order v0..v7: (0,0,0)(1,0,0)(1,1,0)(0,1,0)(0,0,1)(1,0,1)(1,1,1)(0,1,1)
    const float2 f0 = s_tab[(ux ^ b00) & 16383u];
    const float2 f1 = s_tab[(vx ^ b00) & 16383u];
    const float2 f2 = s_tab[(vx ^ b10) & 16383u];
    const float2 f3 = s_tab[(ux ^ b10) & 16383u];
    const float2 f4 = s_tab[(ux ^ b01) & 16383u];
    const float2 f5 = s_tab[(vx ^ b01) & 16383u];
    const float2 f6 = s_tab[(vx ^ b11) & 16383u];
    const float2 f7 = s_tab[(ux ^ b11) & 16383u];

    const float ex = 1.f - wx, ey = 1.f - wy, ez = 1.f - wz;
    const float w00 = ex * ey, w10 = wx * ey, w11 = wx * wy, w01 = ex * wy;
    const float c0 = w00 * ez, c1 = w10 * ez, c2 = w11 * ez, c3 = w01 * ez;
    const float c4 = w00 * wz, c5 = w10 * wz, c6 = w11 * wz, c7 = w01 * wz;

    float vxr = c0 * f0.x;
    vxr = fmaf(c1, f1.x, vxr);
    vxr = fmaf(c2, f2.x, vxr);
    vxr = fmaf(c3, f3.x, vxr);
    vxr = fmaf(c4, f4.x, vxr);
    vxr = fmaf(c5, f5.x, vxr);
    vxr = fmaf(c6, f6.x, vxr);
    vxr = fmaf(c7, f7.x, vxr);

    float vyr = c0 * f0.y;
    vyr = fmaf(c1, f1.y, vyr);
    vyr = fmaf(c2, f2.y, vyr);
    vyr = fmaf(c3, f3.y, vyr);
    vyr = fmaf(c4, f4.y, vyr);
    vyr = fmaf(c5, f5.y, vyr);
    vyr = fmaf(c6, f6.y, vyr);
    vyr = fmaf(c7, f7.y, vyr);

    ox = vxr;
    oy = vyr;
}

__global__ __launch_bounds__(THREADS, 1)
void hashenc_kernel(const float* __restrict__ tables,
                    int bstart, int bend, int B)
{
    const int level = blockIdx.y;

    // Cooperative fill of this level's table into shared memory (16B chunks)
    {
        const float4* src = reinterpret_cast<const float4*>(
            tables + (size_t)level * TABLE_SZ * 2);
        float4* dst = reinterpret_cast<float4*>(s_tab);
        #pragma unroll 4
        for (int i = threadIdx.x; i < TABLE_SZ / 2; i += THREADS)
            dst[i] = src[i];
    }
    __syncthreads();

    const float res = c_res[level];
    int per = (bend - bstart + CHUNKS - 1) / CHUNKS;
    per += (per & 1);                                  // keep pairs aligned
    const int start = bstart + blockIdx.x * per;
    const int end   = min(start + per, bend);

    float2* __restrict__ scr = g_scr + (size_t)level * B;

    // Two consecutive points per thread; pairs never straddle chunk bounds
    for (int b = start + 2 * (int)threadIdx.x; b + 1 < end; b += 2 * THREADS) {
        const float4 p0 = g_xs[b];
        const float4 p1 = g_xs[b + 1];

        float ox0, oy0, ox1, oy1;
        hash_point(p0.x, p0.y, p0.z, res, ox0, oy0);
        hash_point(p1.x, p1.y, p1.z, res, ox1, oy1);

        // One coalesced STG.128 for the pair (b even -> 16B aligned)
        reinterpret_cast<float4*>(scr + b)[0] = make_float4(ox0, oy0, ox1, oy1);
    }
}

// ---------------------------------------------------------------- transpose
// R12-proven: 512 threads, tile = 256 points x 16 levels, MLP=8/thread.
__global__ __launch_bounds__(512)
void transpose_kernel(float4* __restrict__ out4, int bstart, int bend, int B)
{
    __shared__ float2 s[NUM_LEVELS][257];
    const int b0 = bstart + blockIdx.x * 256;
    const int t  = threadIdx.x;            // 0..511
    const int p  = t & 255;                // point within tile
    const int l0 = (t >> 8) * 8;           // level group: 0 or 8
    const int b  = b0 + p;

    if (b < bend) {
        float2 v[8];
        #pragma unroll
        for (int i = 0; i < 8; i++)
            v[i] = g_scr[(size_t)(l0 + i) * B + b];   // 8 independent loads
        #pragma unroll
        for (int i = 0; i < 8; i++)
            s[l0 + i][p] = v[i];                      // conflict-free STS.64
    }
    __syncthreads();

    // 256 points * 8 float4 = 2048 outputs, 4 per thread, coalesced
    #pragma unroll
    for (int i = 0; i < 4; i++) {
        int o  = i * 512 + t;              // 0..2047
        int pp = o >> 3;
        int j  = o & 7;
        if (b0 + pp < bend) {
            float2 a = s[2 * j + 0][pp];
            float2 c = s[2 * j + 1][pp];
            out4[(size_t)b0 * 8 + o] = make_float4(a.x, a.y, c.x, c.y);
        }
    }
}

extern "C" void kernel_launch(void* const* d_in, const int* in_sizes, int n_in,
                              void* d_out, int out_size)
{
    const float* x      = (const float*)d_in[0];
    const float* tables = (const float*)d_in[1];
    float4* out4        = (float4*)d_out;
    const int B = in_sizes[0] / 3;
    const int H = (B / 2) & ~1023;         // half, multiple of 1024

    const int smem = TABLE_SZ * 2 * (int)sizeof(float);  // 131072 B
    cudaFuncSetAttribute(hashenc_kernel,
                         cudaFuncAttributeMaxDynamicSharedMemorySize, smem);

    dim3 grid(CHUNKS, NUM_LEVELS);

    // stream0: pack(h0)
    pack_x_kernel<<<(H + 255) / 256, 256>>>((const float4*)x, 0, H);
    cudaEventRecord(evA, 0);

    // stream2: pack(h1) runs concurrently with main(h0)
    cudaStreamWaitEvent(s2, evA, 0);
    pack_x_kernel<<<((B - H) + 255) / 256, 256, 0, s2>>>(
        (const float4*)x, H, B);
    cudaEventRecord(evB, s2);

    // stream0: main(h0)
    hashenc_kernel<<<grid, THREADS, smem>>>(tables, 0, H, B);
    cudaEventRecord(evC, 0);

    // stream2: transpose(h0) runs concurrently with main(h1)
    cudaStreamWaitEvent(s2, evC, 0);
    transpose_kernel<<<(H + 255) / 256, 512, 0, s2>>>(out4, 0, H, B);
    cudaEventRecord(evD, s2);

    // stream0: main(h1) (needs pack(h1)) then transpose(h1)
    cudaStreamWaitEvent(0, evB, 0);
    hashenc_kernel<<<grid, THREADS, smem>>>(tables, H, B, B);
    transpose_kernel<<<((B - H) + 255) / 256, 512>>>(out4, H, B, B);

    // join stream2 back into the origin stream
    cudaStreamWaitEvent(0, evD, 0);
}

// round 16
// speedup vs baseline: 1.1230x; 1.1230x over previous
#include <cuda_runtime.h>

#define NUM_LEVELS 16
#define TABLE_SZ   16384
#define CHUNKS     9
#define THREADS    1024
#define MAX_B      262144
#define TILE_PTS   2048
#define TILE_F4    1536           // 2048 pts * 12 B / 16

// floor(16 * 1.38^l) computed in double precision, exactly representable in f32
__constant__ float c_res[NUM_LEVELS] = {
    16.f, 22.f, 30.f, 42.f, 58.f, 80.f, 110.f, 152.f,
    210.f, 290.f, 400.f, 553.f, 763.f, 1053.f, 1453.f, 2005.f
};

// Scratch (allocation-free rule: __device__ globals)
__device__ float2 g_scr[NUM_LEVELS * MAX_B];   // [level][b] features (33.5 MB)

__device__ __forceinline__ void hash_point(const float2* __restrict__ s_tab,
                                           const float px, const float py,
                                           const float pz, const float res,
                                           float& ox, float& oy)
{
    // Interpolation weights use the UNSCALED position (faithful to source)
    const float wx = px - floorf(px);
    const float wy = py - floorf(py);
    const float wz = pz - floorf(pz);

    const float sx = res * px;
    const float sy = res * py;
    const float sz = res * pz;

    const int lx = __float2int_rd(sx);
    const int ly = __float2int_rd(sy);
    const int lz = __float2int_rd(sz);
    const int hx = __float2int_ru(sx);
    const int hy = __float2int_ru(sy);
    const int hz = __float2int_ru(sz);

    // int32 wraparound multiply == uint32 multiply (same bits);
    // python remainder by 16384 == & 16383 on two's complement
    const unsigned ay0 = 2654435761u * (unsigned)ly;
    const unsigned ay1 = 2654435761u * (unsigned)hy;
    const unsigned az0 = 805459861u  * (unsigned)lz;
    const unsigned az1 = 805459861u  * (unsigned)hz;

    const unsigned b00 = ay0 ^ az0;
    const unsigned b10 = ay1 ^ az0;
    const unsigned b01 = ay0 ^ az1;
    const unsigned b11 = ay1 ^ az1;
    const unsigned ux = (unsigned)lx;
    const unsigned vx = (unsigned)hx;

    // Corner order v0..v7: (0,0,0)(1,0,0)(1,1,0)(0,1,0)(0,0,1)(1,0,1)(1,1,1)(0,1,1)
    const float2 f0 = s_tab[(ux ^ b00) & 16383u];
    const float2 f1 = s_tab[(vx ^ b00) & 16383u];
    const float2 f2 = s_tab[(vx ^ b10) & 16383u];
    const float2 f3 = s_tab[(ux ^ b10) & 16383u];
    const float2 f4 = s_tab[(ux ^ b01) & 16383u];
    const float2 f5 = s_tab[(vx ^ b01) & 16383u];
    const float2 f6 = s_tab[(vx ^ b11) & 16383u];
    const float2 f7 = s_tab[(ux ^ b11) & 16383u];

    const float ex = 1.f - wx, ey = 1.f - wy, ez = 1.f - wz;
    const float w00 = ex * ey, w10 = wx * ey, w11 = wx * wy, w01 = ex * wy;
    const float c0 = w00 * ez, c1 = w10 * ez, c2 = w11 * ez, c3 = w01 * ez;
    const float c4 = w00 * wz, c5 = w10 * wz, c6 = w11 * wz, c7 = w01 * wz;

    float vxr = c0 * f0.x;
    vxr = fmaf(c1, f1.x, vxr);
    vxr = fmaf(c2, f2.x, vxr);
    vxr = fmaf(c3, f3.x, vxr);
    vxr = fmaf(c4, f4.x, vxr);
    vxr = fmaf(c5, f5.x, vxr);
    vxr = fmaf(c6, f6.x, vxr);
    vxr = fmaf(c7, f7.x, vxr);

    float vyr = c0 * f0.y;
    vyr = fmaf(c1, f1.y, vyr);
    vyr = fmaf(c2, f2.y, vyr);
    vyr = fmaf(c3, f3.y, vyr);
    vyr = fmaf(c4, f4.y, vyr);
    vyr = fmaf(c5, f5.y, vyr);
    vyr = fmaf(c6, f6.y, vyr);
    vyr = fmaf(c7, f7.y, vyr);

    ox = vxr;
    oy = vyr;
}

// smem: [0, 128K) table; [128K, 128K+24576) x tile
#define SMEM_MAIN (TABLE_SZ * 8 + TILE_F4 * 16)

extern __shared__ unsigned char smem_raw[];

__global__ __launch_bounds__(THREADS, 1)
void hashenc_kernel(const float4* __restrict__ x4,
                    const float* __restrict__ tables, int B)
{
    float2* s_tab = reinterpret_cast<float2*>(smem_raw);
    float4* s_x4  = reinterpret_cast<float4*>(smem_raw + TABLE_SZ * 8);
    const float2* sx2 = reinterpret_cast<const float2*>(s_x4);

    const int level = blockIdx.y;
    const int t     = threadIdx.x;

    // Cooperative fill of this level's table into shared memory (16B chunks)
    {
        const float4* src = reinterpret_cast<const float4*>(
            tables + (size_t)level * TABLE_SZ * 2);
        float4* dst = reinterpret_cast<float4*>(s_tab);
        #pragma unroll 4
        for (int i = t; i < TABLE_SZ / 2; i += THREADS)
            dst[i] = src[i];
    }

    const float res = c_res[level];
    const int per   = (B + CHUNKS - 1) / CHUNKS;   // 29128 (even, div by 8)
    const int start = blockIdx.x * per;
    const int end   = min(start + per, B);
    const int span  = end - start;
    const int ntile = (span + TILE_PTS - 1) / TILE_PTS;

    float2* __restrict__ scr = g_scr + (size_t)level * B;

    // ---- software pipeline: prefetch tile j+1 into regs while computing j
    // Prologue: load tile 0 into regs, store to smem.
    float4 r0, r1;
    {
        const int len = min(TILE_PTS, span);
        const int nf4 = (len * 3) >> 2;
        const float4* src = x4 + (((size_t)start * 3) >> 2);
        if (t < nf4)        r0 = src[t];
        if (t + 1024 < nf4) r1 = src[t + 1024];
        __syncthreads();                       // table fill done too
        if (t < nf4)        s_x4[t] = r0;
        if (t + 1024 < nf4) s_x4[t + 1024] = r1;
        __syncthreads();
    }

    for (int j = 0; j < ntile; j++) {
        const int base = start + j * TILE_PTS;
        const int len  = min(TILE_PTS, end - base);

        // Issue next tile's loads (latency hidden by compute below)
        int nn = 0;
        if (j + 1 < ntile) {
            const int nbase = base + TILE_PTS;
            nn = (min(TILE_PTS, end - nbase) * 3) >> 2;
            const float4* src = x4 + (((size_t)nbase * 3) >> 2);
            if (t < nn)        r0 = src[t];
            if (t + 1024 < nn) r1 = src[t + 1024];
        }

        // Compute this tile: 1 pair per thread
        if (2 * t + 1 < len) {
            const float2 q0 = sx2[3 * t + 0];  // p0.x p0.y
            const float2 q1 = sx2[3 * t + 1];  // p0.z p1.x
            const float2 q2 = sx2[3 * t + 2];  // p1.y p1.z

            float ox0, oy0, ox1, oy1;
            hash_point(s_tab, q0.x, q0.y, q1.x, res, ox0, oy0);
            hash_point(s_tab, q1.y, q2.x, q2.y, res, ox1, oy1);

            // One coalesced STG.128 per pair (base even -> 16B aligned)
            reinterpret_cast<float4*>(scr + base + 2 * t)[0] =
                make_float4(ox0, oy0, ox1, oy1);
        }

        if (j + 1 < ntile) {
            __syncthreads();                   // all reads of s_x4 done
            if (t < nn)        s_x4[t] = r0;
            if (t + 1024 < nn) s_x4[t + 1024] = r1;
            __syncthreads();                   // next tile ready
        }
    }
}

// ---------------------------------------------------------------- transpose
// R12-proven: 512 threads, tile = 256 points x 16 levels, MLP=8/thread.
__global__ __launch_bounds__(512)
void transpose_kernel(float4* __restrict__ out4, int B)
{
    __shared__ float2 s[NUM_LEVELS][257];
    const int b0 = blockIdx.x * 256;
    const int t  = threadIdx.x;            // 0..511
    const int p  = t & 255;                // point within tile
    const int l0 = (t >> 8) * 8;           // level group: 0 or 8
    const int b  = b0 + p;

    if (b < B) {
        float2 v[8];
        #pragma unroll
        for (int i = 0; i < 8; i++)
            v[i] = g_scr[(size_t)(l0 + i) * B + b];   // 8 independent loads
        #pragma unroll
        for (int i = 0; i < 8; i++)
            s[l0 + i][p] = v[i];                      // conflict-free STS.64
    }
    __syncthreads();

    // 256 points * 8 float4 = 2048 outputs, 4 per thread, coalesced
    #pragma unroll
    for (int i = 0; i < 4; i++) {
        int o  = i * 512 + t;              // 0..2047
        int pp = o >> 3;
        int j  = o & 7;
        if (b0 + pp < B) {
            float2 a = s[2 * j + 0][pp];
            float2 c = s[2 * j + 1][pp];
            out4[(size_t)b0 * 8 + o] = make_float4(a.x, a.y, c.x, c.y);
        }
    }
}

extern "C" void kernel_launch(void* const* d_in, const int* in_sizes, int n_in,
                              void* d_out, int out_size)
{
    const float* x      = (const float*)d_in[0];
    const float* tables = (const float*)d_in[1];
    float4* out4        = (float4*)d_out;
    const int B = in_sizes[0] / 3;

    cudaFuncSetAttribute(hashenc_kernel,
                         cudaFuncAttributeMaxDynamicSharedMemorySize, SMEM_MAIN);

    dim3 grid(CHUNKS, NUM_LEVELS);
    hashenc_kernel<<<grid, THREADS, SMEM_MAIN>>>(
        (const float4*)x, tables, B);

    transpose_kernel<<<(B + 255) / 256, 512>>>(out4, B);
}

// round 17
// speedup vs baseline: 1.1373x; 1.0127x over previous
#include <cuda_runtime.h>

#define NUM_LEVELS 16
#define TABLE_SZ   16384
#define CHUNKS     9
#define THREADS    1024
#define MAX_B      262144

// floor(16 * 1.38^l) computed in double precision, exactly representable in f32
__constant__ float c_res[NUM_LEVELS] = {
    16.f, 22.f, 30.f, 42.f, 58.f, 80.f, 110.f, 152.f,
    210.f, 290.f, 400.f, 553.f, 763.f, 1053.f, 1453.f, 2005.f
};

// Scratch (allocation-free rule: __device__ globals)
__device__ float4 g_xs[MAX_B];                       // packed positions (4 MB)
__device__ float2 g_scr[NUM_LEVELS * MAX_B];         // [level][b] features (33.5 MB)

extern __shared__ float2 s_tab[];  // main: 16384 float2 = 128 KB

// ---------------------------------------------------------------- pack x
__global__ __launch_bounds__(256)
void pack_x_kernel(const float4* __restrict__ x4, int B)
{
    __shared__ float sx[256 * 3];
    const int b0 = blockIdx.x * 256;
    const int t  = threadIdx.x;
    if (t < 192) {
        float4 v = x4[(size_t)(b0 * 3) / 4 + t];
        sx[4 * t + 0] = v.x; sx[4 * t + 1] = v.y;
        sx[4 * t + 2] = v.z; sx[4 * t + 3] = v.w;
    }
    __syncthreads();
    const int b = b0 + t;
    if (b < B)
        g_xs[b] = make_float4(sx[3 * t], sx[3 * t + 1], sx[3 * t + 2], 0.f);
}

// ---------------------------------------------------------------- main
__device__ __forceinline__ void hash_point(const float px, const float py,
                                           const float pz, const float res,
                                           float& ox, float& oy)
{
    // Interpolation weights use the UNSCALED position (faithful to source)
    const float wx = px - floorf(px);
    const float wy = py - floorf(py);
    const float wz = pz - floorf(pz);

    const float sx = res * px;
    const float sy = res * py;
    const float sz = res * pz;

    const int lx = __float2int_rd(sx);
    const int ly = __float2int_rd(sy);
    const int lz = __float2int_rd(sz);
    const int hx = __float2int_ru(sx);
    const int hy = __float2int_ru(sy);
    const int hz = __float2int_ru(sz);

    // int32 wraparound multiply == uint32 multiply (same bits);
    // python remainder by 16384 == & 16383 on two's complement
    const unsigned ay0 = 2654435761u * (unsigned)ly;
    const unsigned ay1 = 2654435761u * (unsigned)hy;
    const unsigned az0 = 805459861u  * (unsigned)lz;
    const unsigned az1 = 805459861u  * (unsigned)hz;

    const unsigned b00 = ay0 ^ az0;
    const unsigned b10 = ay1 ^ az0;
    const unsigned b01 = ay0 ^ az1;
    const unsigned b11 = ay1 ^ az1;
    const unsigned ux = (unsigned)lx;
    const unsigned vx = (unsigned)hx;

    // Corner order v0..v7: (0,0,0)(1,0,0)(1,1,0)(0,1,0)(0,0,1)(1,0,1)(1,1,1)(0,1,1)
    const float2 f0 = s_tab[(ux ^ b00) & 16383u];
    const float2 f1 = s_tab[(vx ^ b00) & 16383u];
    const float2 f2 = s_tab[(vx ^ b10) & 16383u];
    const float2 f3 = s_tab[(ux ^ b10) & 16383u];
    const float2 f4 = s_tab[(ux ^ b01) & 16383u];
    const float2 f5 = s_tab[(vx ^ b01) & 16383u];
    const float2 f6 = s_tab[(vx ^ b11) & 16383u];
    const float2 f7 = s_tab[(ux ^ b11) & 16383u];

    const float ex = 1.f - wx, ey = 1.f - wy, ez = 1.f - wz;
    const float w00 = ex * ey, w10 = wx * ey, w11 = wx * wy, w01 = ex * wy;
    const float c0 = w00 * ez, c1 = w10 * ez, c2 = w11 * ez, c3 = w01 * ez;
    const float c4 = w00 * wz, c5 = w10 * wz, c6 = w11 * wz, c7 = w01 * wz;

    float vxr = c0 * f0.x;
    vxr = fmaf(c1, f1.x, vxr);
    vxr = fmaf(c2, f2.x, vxr);
    vxr = fmaf(c3, f3.x, vxr);
    vxr = fmaf(c4, f4.x, vxr);
    vxr = fmaf(c5, f5.x, vxr);
    vxr = fmaf(c6, f6.x, vxr);
    vxr = fmaf(c7, f7.x, vxr);

    float vyr = c0 * f0.y;
    vyr = fmaf(c1, f1.y, vyr);
    vyr = fmaf(c2, f2.y, vyr);
    vyr = fmaf(c3, f3.y, vyr);
    vyr = fmaf(c4, f4.y, vyr);
    vyr = fmaf(c5, f5.y, vyr);
    vyr = fmaf(c6, f6.y, vyr);
    vyr = fmaf(c7, f7.y, vyr);

    ox = vxr;
    oy = vyr;
}

__global__ __launch_bounds__(THREADS, 1)
void hashenc_kernel(const float* __restrict__ tables, int B)
{
    const int level = blockIdx.y;

    // Cooperative fill of this level's table into shared memory (16B chunks)
    {
        const float4* src = reinterpret_cast<const float4*>(
            tables + (size_t)level * TABLE_SZ * 2);
        float4* dst = reinterpret_cast<float4*>(s_tab);
        #pragma unroll 4
        for (int i = threadIdx.x; i < TABLE_SZ / 2; i += THREADS)
            dst[i] = src[i];
    }
    __syncthreads();

    const float res = c_res[level];
    const int per   = (B + gridDim.x - 1) / gridDim.x;  // 29128 (even)
    const int start = blockIdx.x * per;
    const int end   = min(start + per, B);

    float2* __restrict__ scr = g_scr + (size_t)level * B;

    // Two consecutive points per thread; pairs never straddle chunk bounds
    for (int b = start + 2 * (int)threadIdx.x; b + 1 < end; b += 2 * THREADS) {
        const float4 p0 = g_xs[b];
        const float4 p1 = g_xs[b + 1];

        float ox0, oy0, ox1, oy1;
        hash_point(p0.x, p0.y, p0.z, res, ox0, oy0);
        hash_point(p1.x, p1.y, p1.z, res, ox1, oy1);

        // One coalesced STG.128 for the pair (b even -> 16B aligned)
        reinterpret_cast<float4*>(scr + b)[0] = make_float4(ox0, oy0, ox1, oy1);
    }
}

// ---------------------------------------------------------------- transpose
// R12 structure + L2 discard of consumed scratch lines (kills the 33.5 MB
// dirty-writeback to HBM that dominated this kernel's time).
__global__ __launch_bounds__(512)
void transpose_kernel(float4* __restrict__ out4, int B)
{
    __shared__ float2 s[NUM_LEVELS][257];
    const int b0 = blockIdx.x * 256;
    const int t  = threadIdx.x;            // 0..511
    const int p  = t & 255;                // point within tile
    const int l0 = (t >> 8) * 8;           // level group: 0 or 8
    const int b  = b0 + p;

    if (b < B) {
        float2 v[8];
        #pragma unroll
        for (int i = 0; i < 8; i++)
            v[i] = g_scr[(size_t)(l0 + i) * B + b];   // 8 independent loads
        #pragma unroll
        for (int i = 0; i < 8; i++)
            s[l0 + i][p] = v[i];                      // conflict-free STS.64
    }
    __syncthreads();                       // all reads of this tile complete

    // Discard the 256 consumed 128B scratch lines of this tile (16 levels x
    // 2048B). Each line is read by exactly this block; data is dead now.
    if (t < 256 && b0 + 255 < B) {
        const int l    = t >> 4;           // 0..15
        const int line = t & 15;           // 0..15
        const char* addr = reinterpret_cast<const char*>(
            &g_scr[(size_t)l * B + b0]) + line * 128;
        asm volatile("discard.global.L2 [%0], 128;" :: "l"(addr) : "memory");
    }

    // 256 points * 8 float4 = 2048 outputs, 4 per thread, coalesced
    #pragma unroll
    for (int i = 0; i < 4; i++) {
        int o  = i * 512 + t;              // 0..2047
        int pp = o >> 3;
        int j  = o & 7;
        if (b0 + pp < B) {
            float2 a = s[2 * j + 0][pp];
            float2 c = s[2 * j + 1][pp];
            out4[(size_t)b0 * 8 + o] = make_float4(a.x, a.y, c.x, c.y);
        }
    }
}

extern "C" void kernel_launch(void* const* d_in, const int* in_sizes, int n_in,
                              void* d_out, int out_size)
{
    const float* x      = (const float*)d_in[0];
    const float* tables = (const float*)d_in[1];
    float4* out4        = (float4*)d_out;
    const int B = in_sizes[0] / 3;

    const int smem = TABLE_SZ * 2 * (int)sizeof(float);  // 131072 B
    cudaFuncSetAttribute(hashenc_kernel,
                         cudaFuncAttributeMaxDynamicSharedMemorySize, smem);

    pack_x_kernel<<<(B + 255) / 256, 256>>>((const float4*)x, B);

    dim3 grid(CHUNKS, NUM_LEVELS);
    hashenc_kernel<<<grid, THREADS, smem>>>(tables, B);

    transpose_kernel<<<(B + 255) / 256, 512>>>(out4, B);
}